// round 12
// baseline (speedup 1.0000x reference)
#include <cuda_runtime.h>
#include <cstdint>
#include <float.h>

#define FRAME   160
#define HOP     256
#define MIN_LAG 40
#define NBATCH  16

typedef unsigned long long ull;

__device__ __forceinline__ void upk2(ull v, float& a, float& b) {
    unsigned int lo, hi;
    asm("mov.b64 {%0, %1}, %2;" : "=r"(lo), "=r"(hi) : "l"(v));
    a = __uint_as_float(lo);
    b = __uint_as_float(hi);
}
__device__ __forceinline__ ull fma2(ull a, ull b, ull c) {
    ull d;
    asm("fma.rn.f32x2 %0, %1, %2, %3;" : "=l"(d) : "l"(a), "l"(b), "l"(c));
    return d;
}
__device__ __forceinline__ ull mul2(ull a, ull b) {
    ull d;
    asm("mul.rn.f32x2 %0, %1, %2;" : "=l"(d) : "l"(a), "l"(b));
    return d;
}
// SW128 swizzle on buffer-relative byte offset (buffers 1024B-aligned).
__device__ __forceinline__ int swz(int off) { return off ^ ((off >> 3) & 0x70); }
__device__ __forceinline__ constexpr int slot(int d) {
    int m = d % 12; return m < 0 ? m + 12 : m;
}

// FOLDED self-convolution: c[l] = 2*sum_{n<ceil(l/2)} x[n]x[l-n] + [l even]x[l/2]^2.
// Accumulate half-sum + 1/2*center; argmax invariant under the final x2.
// Per lane (lags l0..l0+7): stops h0+u_j, h0 = l0/2 = 20+4*tl (multiple of 4),
// u = [0,1,1,2,2,3,3,4]. 19 uniform chunks with per-lane chunk sign-masking,
// then a lane-invariant boundary pattern. Frame at pair 64 (pad [0,64) zeros;
// deepest refill reaches pair 28). 2KB/buffer, regs capped 64 for 8 blocks/SM.
__global__ __launch_bounds__(128, 8)
void pitch_kernel(const float* __restrict__ audio,
                  float* __restrict__ out,
                  int S, int T, int total_frames) {
    // per-warp: two pair-buffers of 256 pairs (2KB, 1024B-aligned strides).
    // pairs [0..63] zero pad, [64..223] frame, rest slack.
    __shared__ __align__(1024) ull sbuf[4][2][256];

    const int warp = threadIdx.x >> 5;
    const int lane = threadIdx.x & 31;
    const int g0   = (blockIdx.x * 4 + warp) * 4;
    if (g0 >= total_frames) return;

    const int batch = g0 / T;
    const int f0    = g0 - batch * T;               // T % 4 == 0 -> same batch
    const float* base = audio + (size_t)batch * S + (size_t)f0 * HOP;

    char* b0 = (char*)sbuf[warp][0];
    char* b1 = (char*)sbuf[warp][1];

    // ---- stage 4 frames: float4 loads, mean, center, maxabs, pair stores ----
    float4 q[4];
    float  t[4];
    #pragma unroll
    for (int s = 0; s < 4; ++s) {
        q[s] = ((const float4*)(base + s * HOP))[lane];     // samples 4l..4l+3
        t[s] = base[s * HOP + 128 + lane];                  // sample 128+l
    }
    float sm[4];
    #pragma unroll
    for (int s = 0; s < 4; ++s)
        sm[s] = ((q[s].x + q[s].y) + (q[s].z + q[s].w)) + t[s];
    #pragma unroll
    for (int off = 16; off; off >>= 1)
        #pragma unroll
        for (int s = 0; s < 4; ++s)
            sm[s] += __shfl_xor_sync(0xffffffffu, sm[s], off);
    float mean[4];
    #pragma unroll
    for (int s = 0; s < 4; ++s) mean[s] = sm[s] / 160.0f;

    float ma[4];
    {   // centered values; pairs 4l..4l+3 via two STS.128 each, tail STS.64
        float cA[4], cB[4], cC[4], cD[4];
        const float* qa = &q[0].x; const float* qb = &q[1].x;
        const float* qc = &q[2].x; const float* qd = &q[3].x;
        #pragma unroll
        for (int i = 0; i < 4; ++i) {
            cA[i] = qa[i] - mean[0]; cB[i] = qb[i] - mean[1];
            cC[i] = qc[i] - mean[2]; cD[i] = qd[i] - mean[3];
        }
        const int o0 = swz(8 * (64 + 4 * lane));            // bit4 == 0
        *(float4*)(b0 + o0)        = make_float4(cA[0], cB[0], cA[1], cB[1]);
        *(float4*)(b0 + (o0 ^ 16)) = make_float4(cA[2], cB[2], cA[3], cB[3]);
        *(float4*)(b1 + o0)        = make_float4(cC[0], cD[0], cC[1], cD[1]);
        *(float4*)(b1 + (o0 ^ 16)) = make_float4(cC[2], cD[2], cC[3], cD[3]);
        const float tA = t[0] - mean[0], tB = t[1] - mean[1];
        const float tC = t[2] - mean[2], tD = t[3] - mean[3];
        const int ot = swz(8 * (192 + lane));
        *(float2*)(b0 + ot) = make_float2(tA, tB);
        *(float2*)(b1 + ot) = make_float2(tC, tD);

        ma[0] = fmaxf(fmaxf(fmaxf(fabsf(cA[0]), fabsf(cA[1])),
                            fmaxf(fabsf(cA[2]), fabsf(cA[3]))), fabsf(tA));
        ma[1] = fmaxf(fmaxf(fmaxf(fabsf(cB[0]), fabsf(cB[1])),
                            fmaxf(fabsf(cB[2]), fabsf(cB[3]))), fabsf(tB));
        ma[2] = fmaxf(fmaxf(fmaxf(fabsf(cC[0]), fabsf(cC[1])),
                            fmaxf(fabsf(cC[2]), fabsf(cC[3]))), fabsf(tC));
        ma[3] = fmaxf(fmaxf(fmaxf(fabsf(cD[0]), fabsf(cD[1])),
                            fmaxf(fabsf(cD[2]), fabsf(cD[3]))), fabsf(tD));
    }
    #pragma unroll
    for (int i = 0; i < 2; ++i) {                           // zero pad [0,64)
        const int off = swz(8 * (lane + 32 * i));
        *(ull*)(b0 + off) = 0ull;
        *(ull*)(b1 + off) = 0ull;
    }
    #pragma unroll
    for (int off = 16; off; off >>= 1)
        #pragma unroll
        for (int s = 0; s < 4; ++s)
            ma[s] = fmaxf(ma[s], __shfl_xor_sync(0xffffffffu, ma[s], off));
    __syncwarp();

    // ---- folded windowed self-conv, 8 lags/lane ----
    const int hl = lane & 15;
    const int tl = (hl < 15) ? hl : 14;
    const int l0 = MIN_LAG + 8 * tl;
    const int h0 = l0 >> 1;                                 // 20 + 4*tl
    const char* mb = (lane < 16) ? b0 : b1;
    const int l0b = 8 * (64 + l0);

    ull w[12];
    {   // init d = -4..7; offsets 32-aligned -> pairwise ^16
        const int i0 = swz(l0b - 32);
        const int i1 = swz(l0b);
        const int i2 = swz(l0b + 32);
        const ulonglong2 t0 = *(const ulonglong2*)(mb + i0);
        const ulonglong2 t1 = *(const ulonglong2*)(mb + (i0 ^ 16));
        const ulonglong2 t2 = *(const ulonglong2*)(mb + i1);
        const ulonglong2 t3 = *(const ulonglong2*)(mb + (i1 ^ 16));
        const ulonglong2 t4 = *(const ulonglong2*)(mb + i2);
        const ulonglong2 t5 = *(const ulonglong2*)(mb + (i2 ^ 16));
        w[slot(-4)] = t0.x; w[slot(-3)] = t0.y;
        w[slot(-2)] = t1.x; w[slot(-1)] = t1.y;
        w[slot( 0)] = t2.x; w[slot( 1)] = t2.y;
        w[slot( 2)] = t3.x; w[slot( 3)] = t3.y;
        w[slot( 4)] = t4.x; w[slot( 5)] = t4.y;
        w[slot( 6)] = t5.x; w[slot( 7)] = t5.y;
    }

    ull acc[8];
    #pragma unroll
    for (int j = 0; j < 8; ++j) acc[j] = 0ull;

    // prefetch broadcast x for chunk 0 (frame base byte 512)
    ulonglong2 xv0 = *(const ulonglong2*)(mb + swz(512));
    ulonglong2 xv1 = *(const ulonglong2*)(mb + (swz(512) ^ 16));

    int bro = 512 + 32;         // raw byte off of broadcast pairs for n = 4
    int rro = l0b - 64;         // raw byte off of refill pairs for chunk n = 0
    int cnt = -h0;              // n0 - h0; chunk active iff cnt < 0

#define DO_CHUNK(C, PRE, REF)                                                 \
    {                                                                         \
        const unsigned m32 = (unsigned)(cnt >> 31);                           \
        cnt += 4;                                                             \
        const ull mm = ((ull)m32 << 32) | m32;                                \
        const ull x0 = xv0.x & mm, x1 = xv0.y & mm;                           \
        const ull x2 = xv1.x & mm, x3 = xv1.y & mm;                           \
        if (PRE) {                                                            \
            const int bo = swz(bro);                                          \
            xv0 = *(const ulonglong2*)(mb + bo);                              \
            xv1 = *(const ulonglong2*)(mb + (bo ^ 16));                       \
            bro += 32;                                                        \
        }                                                                     \
        ulonglong2 ra, rb;                                                    \
        if (REF) {                                                            \
            const int r0 = swz(rro);                                          \
            ra = *(const ulonglong2*)(mb + r0);                               \
            rb = *(const ulonglong2*)(mb + (r0 ^ 16));                        \
            rro -= 32;                                                        \
        }                                                                     \
        _Pragma("unroll")                                                     \
        for (int j = 0; j < 8; ++j)                                           \
            acc[j] = fma2(x0, w[slot(j - 4 * (C) - 0)], acc[j]);              \
        _Pragma("unroll")                                                     \
        for (int j = 0; j < 8; ++j)                                           \
            acc[j] = fma2(x1, w[slot(j - 4 * (C) - 1)], acc[j]);              \
        _Pragma("unroll")                                                     \
        for (int j = 0; j < 8; ++j)                                           \
            acc[j] = fma2(x2, w[slot(j - 4 * (C) - 2)], acc[j]);              \
        _Pragma("unroll")                                                     \
        for (int j = 0; j < 8; ++j)                                           \
            acc[j] = fma2(x3, w[slot(j - 4 * (C) - 3)], acc[j]);              \
        if (REF) {                                                            \
            w[slot(-4 * (C) - 8)] = ra.x;                                     \
            w[slot(-4 * (C) - 7)] = ra.y;                                     \
            w[slot(-4 * (C) - 6)] = rb.x;                                     \
            w[slot(-4 * (C) - 5)] = rb.y;                                     \
        }                                                                     \
    }

    #pragma unroll 1
    for (int it = 0; it < 6; ++it) {        // n0 = 12*it + {0,4,8}  (0..68)
        DO_CHUNK(0, true, true)
        DO_CHUNK(1, true, true)
        DO_CHUNK(2, true, true)
    }
    DO_CHUNK(0, false, false)               // n0 = 72 (72 % 12 == 0)
#undef DO_CHUNK

    // ---- boundary chunk: n = h0..h0+3, strict tail + half-centers ----
    // acc_j += x[h0+e] * x[h0+j-e] for e < u_j (u=[0,1,1,2,2,3,3,4]);
    // acc_j += 0.5*x[h0+j/2]^2 for even j.  v[k] = pair x[h0+k], k=0..7.
    {
        const int bo = 8 * (64 + h0);                       // 32-aligned
        const int o2 = swz(bo);
        const int o3 = swz(bo + 32);
        const ulonglong2 p2 = *(const ulonglong2*)(mb + o2);
        const ulonglong2 p3 = *(const ulonglong2*)(mb + (o2 ^ 16));
        const ulonglong2 p4 = *(const ulonglong2*)(mb + o3);
        const ulonglong2 p5 = *(const ulonglong2*)(mb + (o3 ^ 16));
        const ull v4 = p2.x, v5 = p2.y, v6 = p3.x, v7 = p3.y;
        const ull v8 = p4.x, v9 = p4.y, v10 = p5.x, v11 = p5.y;

        const ull HALF2 = 0x3F0000003F000000ull;            // packed (0.5f, 0.5f)
        const ull h4 = mul2(v4, HALF2);
        const ull h5 = mul2(v5, HALF2);
        const ull h6 = mul2(v6, HALF2);
        const ull h7 = mul2(v7, HALF2);

        // e = 0 (x = v4)
        acc[0] = fma2(h4, v4,  acc[0]);                     // center l0+0
        acc[1] = fma2(v4, v5,  acc[1]);
        acc[2] = fma2(v4, v6,  acc[2]);
        acc[3] = fma2(v4, v7,  acc[3]);
        acc[4] = fma2(v4, v8,  acc[4]);
        acc[5] = fma2(v4, v9,  acc[5]);
        acc[6] = fma2(v4, v10, acc[6]);
        acc[7] = fma2(v4, v11, acc[7]);
        // e = 1 (x = v5)
        acc[2] = fma2(h5, v5,  acc[2]);                     // center l0+2
        acc[3] = fma2(v5, v6,  acc[3]);
        acc[4] = fma2(v5, v7,  acc[4]);
        acc[5] = fma2(v5, v8,  acc[5]);
        acc[6] = fma2(v5, v9,  acc[6]);
        acc[7] = fma2(v5, v10, acc[7]);
        // e = 2 (x = v6)
        acc[4] = fma2(h6, v6,  acc[4]);                     // center l0+4
        acc[5] = fma2(v6, v7,  acc[5]);
        acc[6] = fma2(v6, v8,  acc[6]);
        acc[7] = fma2(v6, v9,  acc[7]);
        // e = 3 (x = v7)
        acc[6] = fma2(h7, v7,  acc[6]);                     // center l0+6
        acc[7] = fma2(v7, v8,  acc[7]);
    }

    // ---- argmax over 8 lags/lane, then 16-lane group reduce ----
    float lo, hi;
    float bLo = -FLT_MAX, bHi = -FLT_MAX;
    int   gLo = 0x7fffffff, gHi = 0x7fffffff;
    #pragma unroll
    for (int j = 0; j < 8; ++j) {
        upk2(acc[j], lo, hi);
        const int l = l0 + j;
        if (lo > bLo) { bLo = lo; gLo = l; }
        if (hi > bHi) { bHi = hi; gHi = l; }
    }
    if (hl == 15) { bLo = -FLT_MAX; bHi = -FLT_MAX; gLo = gHi = 0x7fffffff; }

    #pragma unroll
    for (int off = 8; off; off >>= 1) {                     // within 16-lane group
        float vL = __shfl_xor_sync(0xffffffffu, bLo, off);
        int   iL = __shfl_xor_sync(0xffffffffu, gLo, off);
        if (vL > bLo || (vL == bLo && iL < gLo)) { bLo = vL; gLo = iL; }
        float vH = __shfl_xor_sync(0xffffffffu, bHi, off);
        int   iH = __shfl_xor_sync(0xffffffffu, gHi, off);
        if (vH > bHi || (vH == bHi && iH < gHi)) { bHi = vH; gHi = iH; }
    }

    if (hl == 0) {
        const int o = g0 + ((lane >> 4) << 1);
        const float mLo = (lane < 16) ? ma[0] : ma[2];
        const float mHi = (lane < 16) ? ma[1] : ma[3];
        out[o]     = (mLo < 1e-8f) ? 0.f : 16000.0f / (float)gLo;
        out[o + 1] = (mHi < 1e-8f) ? 0.f : 16000.0f / (float)gHi;
    }
}

extern "C" void kernel_launch(void* const* d_in, const int* in_sizes, int n_in,
                              void* d_out, int out_size) {
    const float* audio = (const float*)d_in[0];
    float* out = (float*)d_out;

    const int total = in_sizes[0];              // 16 * 1048576
    const int B = NBATCH;
    const int S = total / B;                    // 1048576
    const int T = (S - FRAME) / HOP + 1;        // 4096
    const int frames = B * T;                   // 65536 == out_size
    const int tasks  = frames / 4;              // 16384 warps
    const int blocks = (tasks + 3) / 4;         // 4096 blocks of 4 warps

    pitch_kernel<<<blocks, 128>>>(audio, out, S, T, frames);
}

// round 13
// speedup vs baseline: 1.0368x; 1.0368x over previous
#include <cuda_runtime.h>
#include <cstdint>
#include <float.h>

#define FRAME   160
#define HOP     256
#define MIN_LAG 40
#define NBATCH  16

typedef unsigned long long ull;

__device__ __forceinline__ void upk2(ull v, float& a, float& b) {
    unsigned int lo, hi;
    asm("mov.b64 {%0, %1}, %2;" : "=r"(lo), "=r"(hi) : "l"(v));
    a = __uint_as_float(lo);
    b = __uint_as_float(hi);
}
__device__ __forceinline__ ull fma2(ull a, ull b, ull c) {
    ull d;
    asm("fma.rn.f32x2 %0, %1, %2, %3;" : "=l"(d) : "l"(a), "l"(b), "l"(c));
    return d;
}
__device__ __forceinline__ ull mul2(ull a, ull b) {
    ull d;
    asm("mul.rn.f32x2 %0, %1, %2;" : "=l"(d) : "l"(a), "l"(b));
    return d;
}
// SW128 swizzle on buffer-relative byte offset (buffers 1024B-aligned).
__device__ __forceinline__ int swz(int off) { return off ^ ((off >> 3) & 0x70); }
__device__ __forceinline__ constexpr int slot(int d) {
    int m = d % 12; return m < 0 ? m + 12 : m;
}

// FOLDED self-convolution: c[l] = 2*sum_{n<ceil(l/2)} x[n]x[l-n] + [l even]x[l/2]^2.
// Accumulate half-sum + 1/2*center; argmax invariant under the final x2.
// Per lane (lags l0..l0+7): stops h0+u_j, h0 = l0/2 = 20+4*tl (multiple of 4).
// 19 uniform chunks; lanes past their stop REDIRECT the broadcast-x load into
// the zero-pad region (address select, no AND masking) -> products vanish.
// Then a lane-invariant boundary pattern. Frame at pair 64 (pad [0,64) zeros).
__global__ __launch_bounds__(128)
void pitch_kernel(const float* __restrict__ audio,
                  float* __restrict__ out,
                  int S, int T, int total_frames) {
    // per-warp: two pair-buffers of 256 pairs (2KB, 1024B-aligned strides).
    // pairs [0..63] zero pad, [64..223] frame, rest slack.
    __shared__ __align__(1024) ull sbuf[4][2][256];

    const int warp = threadIdx.x >> 5;
    const int lane = threadIdx.x & 31;
    const int g0   = (blockIdx.x * 4 + warp) * 4;
    if (g0 >= total_frames) return;

    const int batch = g0 / T;
    const int f0    = g0 - batch * T;               // T % 4 == 0 -> same batch
    const float* base = audio + (size_t)batch * S + (size_t)f0 * HOP;

    char* b0 = (char*)sbuf[warp][0];
    char* b1 = (char*)sbuf[warp][1];

    // ---- stage 4 frames: float4 loads, mean, center, maxabs, pair stores ----
    float4 q[4];
    float  t[4];
    #pragma unroll
    for (int s = 0; s < 4; ++s) {
        q[s] = ((const float4*)(base + s * HOP))[lane];     // samples 4l..4l+3
        t[s] = base[s * HOP + 128 + lane];                  // sample 128+l
    }
    float sm[4];
    #pragma unroll
    for (int s = 0; s < 4; ++s)
        sm[s] = ((q[s].x + q[s].y) + (q[s].z + q[s].w)) + t[s];
    #pragma unroll
    for (int off = 16; off; off >>= 1)
        #pragma unroll
        for (int s = 0; s < 4; ++s)
            sm[s] += __shfl_xor_sync(0xffffffffu, sm[s], off);
    float mean[4];
    #pragma unroll
    for (int s = 0; s < 4; ++s) mean[s] = sm[s] / 160.0f;

    float ma[4];
    {   // centered values; pairs 4l..4l+3 via two STS.128 each, tail STS.64
        float cA[4], cB[4], cC[4], cD[4];
        const float* qa = &q[0].x; const float* qb = &q[1].x;
        const float* qc = &q[2].x; const float* qd = &q[3].x;
        #pragma unroll
        for (int i = 0; i < 4; ++i) {
            cA[i] = qa[i] - mean[0]; cB[i] = qb[i] - mean[1];
            cC[i] = qc[i] - mean[2]; cD[i] = qd[i] - mean[3];
        }
        const int o0 = swz(8 * (64 + 4 * lane));            // bit4 == 0
        *(float4*)(b0 + o0)        = make_float4(cA[0], cB[0], cA[1], cB[1]);
        *(float4*)(b0 + (o0 ^ 16)) = make_float4(cA[2], cB[2], cA[3], cB[3]);
        *(float4*)(b1 + o0)        = make_float4(cC[0], cD[0], cC[1], cD[1]);
        *(float4*)(b1 + (o0 ^ 16)) = make_float4(cC[2], cD[2], cC[3], cD[3]);
        const float tA = t[0] - mean[0], tB = t[1] - mean[1];
        const float tC = t[2] - mean[2], tD = t[3] - mean[3];
        const int ot = swz(8 * (192 + lane));
        *(float2*)(b0 + ot) = make_float2(tA, tB);
        *(float2*)(b1 + ot) = make_float2(tC, tD);

        ma[0] = fmaxf(fmaxf(fmaxf(fabsf(cA[0]), fabsf(cA[1])),
                            fmaxf(fabsf(cA[2]), fabsf(cA[3]))), fabsf(tA));
        ma[1] = fmaxf(fmaxf(fmaxf(fabsf(cB[0]), fabsf(cB[1])),
                            fmaxf(fabsf(cB[2]), fabsf(cB[3]))), fabsf(tB));
        ma[2] = fmaxf(fmaxf(fmaxf(fabsf(cC[0]), fabsf(cC[1])),
                            fmaxf(fabsf(cC[2]), fabsf(cC[3]))), fabsf(tC));
        ma[3] = fmaxf(fmaxf(fmaxf(fabsf(cD[0]), fabsf(cD[1])),
                            fmaxf(fabsf(cD[2]), fabsf(cD[3]))), fabsf(tD));
    }
    #pragma unroll
    for (int i = 0; i < 2; ++i) {                           // zero pad [0,64)
        const int off = swz(8 * (lane + 32 * i));
        *(ull*)(b0 + off) = 0ull;
        *(ull*)(b1 + off) = 0ull;
    }
    #pragma unroll
    for (int off = 16; off; off >>= 1)
        #pragma unroll
        for (int s = 0; s < 4; ++s)
            ma[s] = fmaxf(ma[s], __shfl_xor_sync(0xffffffffu, ma[s], off));
    __syncwarp();

    // ---- folded windowed self-conv, 8 lags/lane ----
    const int hl = lane & 15;
    const int tl = (hl < 15) ? hl : 14;
    const int l0 = MIN_LAG + 8 * tl;
    const int h0 = l0 >> 1;                                 // 20 + 4*tl
    const char* mb = (lane < 16) ? b0 : b1;
    const int l0b = 8 * (64 + l0);

    ull w[12];
    {   // init d = -4..7; offsets 32-aligned -> pairwise ^16
        const int i0 = swz(l0b - 32);
        const int i1 = swz(l0b);
        const int i2 = swz(l0b + 32);
        const ulonglong2 t0 = *(const ulonglong2*)(mb + i0);
        const ulonglong2 t1 = *(const ulonglong2*)(mb + (i0 ^ 16));
        const ulonglong2 t2 = *(const ulonglong2*)(mb + i1);
        const ulonglong2 t3 = *(const ulonglong2*)(mb + (i1 ^ 16));
        const ulonglong2 t4 = *(const ulonglong2*)(mb + i2);
        const ulonglong2 t5 = *(const ulonglong2*)(mb + (i2 ^ 16));
        w[slot(-4)] = t0.x; w[slot(-3)] = t0.y;
        w[slot(-2)] = t1.x; w[slot(-1)] = t1.y;
        w[slot( 0)] = t2.x; w[slot( 1)] = t2.y;
        w[slot( 2)] = t3.x; w[slot( 3)] = t3.y;
        w[slot( 4)] = t4.x; w[slot( 5)] = t4.y;
        w[slot( 6)] = t5.x; w[slot( 7)] = t5.y;
    }

    ull acc[8];
    #pragma unroll
    for (int j = 0; j < 8; ++j) acc[j] = 0ull;

    // prefetch broadcast x for chunk 0 (frame base byte 512; all lanes active
    // at n=0 since h0 >= 20)
    ulonglong2 xv0 = *(const ulonglong2*)(mb + swz(512));
    ulonglong2 xv1 = *(const ulonglong2*)(mb + (swz(512) ^ 16));

    int bro = 512 + 32;         // raw byte off of broadcast pairs for n = 4
    int rro = l0b - 64;         // raw byte off of refill pairs for chunk n = 0
    int cnt = -h0;              // (next n0) - h0 after the += below

    // One chunk; C = (n0/4) % 3 selects compile-time slot pattern.
    // Prefetch redirects to pad (zeros) for lanes whose next chunk is past h0.
#define DO_CHUNK(C, PRE, REF)                                                 \
    {                                                                         \
        const ull x0 = xv0.x, x1 = xv0.y, x2 = xv1.x, x3 = xv1.y;             \
        if (PRE) {                                                            \
            cnt += 4;                                                         \
            const int bo = (cnt < 0) ? swz(bro) : 0;                          \
            xv0 = *(const ulonglong2*)(mb + bo);                              \
            xv1 = *(const ulonglong2*)(mb + (bo ^ 16));                       \
            bro += 32;                                                        \
        }                                                                     \
        ulonglong2 ra, rb;                                                    \
        if (REF) {                                                            \
            const int r0 = swz(rro);                                          \
            ra = *(const ulonglong2*)(mb + r0);                               \
            rb = *(const ulonglong2*)(mb + (r0 ^ 16));                        \
            rro -= 32;                                                        \
        }                                                                     \
        _Pragma("unroll")                                                     \
        for (int j = 0; j < 8; ++j)                                           \
            acc[j] = fma2(x0, w[slot(j - 4 * (C) - 0)], acc[j]);              \
        _Pragma("unroll")                                                     \
        for (int j = 0; j < 8; ++j)                                           \
            acc[j] = fma2(x1, w[slot(j - 4 * (C) - 1)], acc[j]);              \
        _Pragma("unroll")                                                     \
        for (int j = 0; j < 8; ++j)                                           \
            acc[j] = fma2(x2, w[slot(j - 4 * (C) - 2)], acc[j]);              \
        _Pragma("unroll")                                                     \
        for (int j = 0; j < 8; ++j)                                           \
            acc[j] = fma2(x3, w[slot(j - 4 * (C) - 3)], acc[j]);              \
        if (REF) {                                                            \
            w[slot(-4 * (C) - 8)] = ra.x;                                     \
            w[slot(-4 * (C) - 7)] = ra.y;                                     \
            w[slot(-4 * (C) - 6)] = rb.x;                                     \
            w[slot(-4 * (C) - 5)] = rb.y;                                     \
        }                                                                     \
    }

    #pragma unroll 1
    for (int it = 0; it < 6; ++it) {        // n0 = 12*it + {0,4,8}  (0..68)
        DO_CHUNK(0, true, true)
        DO_CHUNK(1, true, true)
        DO_CHUNK(2, true, true)
    }
    DO_CHUNK(0, false, false)               // n0 = 72 (72 % 12 == 0)
#undef DO_CHUNK

    // ---- boundary chunk: n = h0..h0+3, strict tail + half-centers ----
    // acc_j += x[h0+e] * x[h0+j-e] for e < u_j (u=[0,1,1,2,2,3,3,4]);
    // acc_j += 0.5*x[h0+j/2]^2 for even j.  v[k] = pair x[h0+k-4], k=4..11.
    {
        const int bo = 8 * (64 + h0);                       // 32-aligned
        const int o2 = swz(bo);
        const int o3 = swz(bo + 32);
        const ulonglong2 p2 = *(const ulonglong2*)(mb + o2);
        const ulonglong2 p3 = *(const ulonglong2*)(mb + (o2 ^ 16));
        const ulonglong2 p4 = *(const ulonglong2*)(mb + o3);
        const ulonglong2 p5 = *(const ulonglong2*)(mb + (o3 ^ 16));
        const ull v4 = p2.x, v5 = p2.y, v6 = p3.x, v7 = p3.y;
        const ull v8 = p4.x, v9 = p4.y, v10 = p5.x, v11 = p5.y;

        const ull HALF2 = 0x3F0000003F000000ull;            // packed (0.5f, 0.5f)
        const ull h4 = mul2(v4, HALF2);
        const ull h5 = mul2(v5, HALF2);
        const ull h6 = mul2(v6, HALF2);
        const ull h7 = mul2(v7, HALF2);

        // e = 0 (x = v4)
        acc[0] = fma2(h4, v4,  acc[0]);                     // center l0+0
        acc[1] = fma2(v4, v5,  acc[1]);
        acc[2] = fma2(v4, v6,  acc[2]);
        acc[3] = fma2(v4, v7,  acc[3]);
        acc[4] = fma2(v4, v8,  acc[4]);
        acc[5] = fma2(v4, v9,  acc[5]);
        acc[6] = fma2(v4, v10, acc[6]);
        acc[7] = fma2(v4, v11, acc[7]);
        // e = 1 (x = v5)
        acc[2] = fma2(h5, v5,  acc[2]);                     // center l0+2
        acc[3] = fma2(v5, v6,  acc[3]);
        acc[4] = fma2(v5, v7,  acc[4]);
        acc[5] = fma2(v5, v8,  acc[5]);
        acc[6] = fma2(v5, v9,  acc[6]);
        acc[7] = fma2(v5, v10, acc[7]);
        // e = 2 (x = v6)
        acc[4] = fma2(h6, v6,  acc[4]);                     // center l0+4
        acc[5] = fma2(v6, v7,  acc[5]);
        acc[6] = fma2(v6, v8,  acc[6]);
        acc[7] = fma2(v6, v9,  acc[7]);
        // e = 3 (x = v7)
        acc[6] = fma2(h7, v7,  acc[6]);                     // center l0+6
        acc[7] = fma2(v7, v8,  acc[7]);
    }

    // ---- argmax over 8 lags/lane, then 16-lane group reduce ----
    float lo, hi;
    float bLo = -FLT_MAX, bHi = -FLT_MAX;
    int   gLo = 0x7fffffff, gHi = 0x7fffffff;
    #pragma unroll
    for (int j = 0; j < 8; ++j) {
        upk2(acc[j], lo, hi);
        const int l = l0 + j;
        if (lo > bLo) { bLo = lo; gLo = l; }
        if (hi > bHi) { bHi = hi; gHi = l; }
    }
    if (hl == 15) { bLo = -FLT_MAX; bHi = -FLT_MAX; gLo = gHi = 0x7fffffff; }

    #pragma unroll
    for (int off = 8; off; off >>= 1) {                     // within 16-lane group
        float vL = __shfl_xor_sync(0xffffffffu, bLo, off);
        int   iL = __shfl_xor_sync(0xffffffffu, gLo, off);
        if (vL > bLo || (vL == bLo && iL < gLo)) { bLo = vL; gLo = iL; }
        float vH = __shfl_xor_sync(0xffffffffu, bHi, off);
        int   iH = __shfl_xor_sync(0xffffffffu, gHi, off);
        if (vH > bHi || (vH == bHi && iH < gHi)) { bHi = vH; gHi = iH; }
    }

    if (hl == 0) {
        const int o = g0 + ((lane >> 4) << 1);
        const float mLo = (lane < 16) ? ma[0] : ma[2];
        const float mHi = (lane < 16) ? ma[1] : ma[3];
        out[o]     = (mLo < 1e-8f) ? 0.f : 16000.0f / (float)gLo;
        out[o + 1] = (mHi < 1e-8f) ? 0.f : 16000.0f / (float)gHi;
    }
}

extern "C" void kernel_launch(void* const* d_in, const int* in_sizes, int n_in,
                              void* d_out, int out_size) {
    const float* audio = (const float*)d_in[0];
    float* out = (float*)d_out;

    const int total = in_sizes[0];              // 16 * 1048576
    const int B = NBATCH;
    const int S = total / B;                    // 1048576
    const int T = (S - FRAME) / HOP + 1;        // 4096
    const int frames = B * T;                   // 65536 == out_size
    const int tasks  = frames / 4;              // 16384 warps
    const int blocks = (tasks + 3) / 4;         // 4096 blocks of 4 warps

    pitch_kernel<<<blocks, 128>>>(audio, out, S, T, frames);
}

// round 14
// speedup vs baseline: 1.0966x; 1.0576x over previous
#include <cuda_runtime.h>
#include <cstdint>
#include <float.h>

#define FRAME   160
#define HOP     256
#define MIN_LAG 40
#define NBATCH  16

typedef unsigned long long ull;

__device__ __forceinline__ void upk2(ull v, float& a, float& b) {
    unsigned int lo, hi;
    asm("mov.b64 {%0, %1}, %2;" : "=r"(lo), "=r"(hi) : "l"(v));
    a = __uint_as_float(lo);
    b = __uint_as_float(hi);
}
__device__ __forceinline__ ull fma2(ull a, ull b, ull c) {
    ull d;
    asm("fma.rn.f32x2 %0, %1, %2, %3;" : "=l"(d) : "l"(a), "l"(b), "l"(c));
    return d;
}
__device__ __forceinline__ ull mul2(ull a, ull b) {
    ull d;
    asm("mul.rn.f32x2 %0, %1, %2;" : "=l"(d) : "l"(a), "l"(b));
    return d;
}
__device__ __forceinline__ ull add2(ull a, ull b) {
    ull d;
    asm("add.rn.f32x2 %0, %1, %2;" : "=l"(d) : "l"(a), "l"(b));
    return d;
}
// SW128 swizzle on buffer-relative byte offset (buffers 1024B-aligned).
__device__ __forceinline__ int swz(int off) { return off ^ ((off >> 3) & 0x70); }
__device__ __forceinline__ constexpr int slot(int d) {
    int m = d % 12; return m < 0 ? m + 12 : m;
}

// FOLDED self-conv c[l] = 2*sum_{n<ceil(l/2)} x[n]x[l-n] + [l even]x[l/2]^2
// with BUDDY-LANE rebalance. Lane hl owns lags l0=40+8*tl (8 lags, h0=20+4tl).
// Phase 1: chunks n=0..44 (everyone, own lags). Boundary + per-lane argmax.
// Phase 2 (4 chunks): owners (hl>=8) do n=48..56 gated by min(h0,60); buddies
// (hl 3..6) re-target owner hl+8's lags (l0b'=l0b+512) and do n=60..72.
// 60==48 mod 12 -> one shared compile-time slot pattern. Buddy partials are
// shfl'd to owners and added. Broadcast x comes from a separate UNSWIZZLED
// buffer (zeros at offset 0 for the past-stop redirect).
__global__ __launch_bounds__(128)
void pitch_kernel(const float* __restrict__ audio,
                  float* __restrict__ out,
                  int S, int T, int total_frames) {
    // swizzled pair buffers: pairs [0..63] zeros, [64..223] frame.
    __shared__ __align__(1024) ull sbuf[4][2][256];
    // linear broadcast buffers: pairs [0..3] zeros (redirect pad), [4..163] frame.
    __shared__ __align__(16) ull xbuf[4][2][168];

    const int warp = threadIdx.x >> 5;
    const int lane = threadIdx.x & 31;
    const int g0   = (blockIdx.x * 4 + warp) * 4;
    if (g0 >= total_frames) return;

    const int batch = g0 / T;
    const int f0    = g0 - batch * T;               // T % 4 == 0 -> same batch
    const float* base = audio + (size_t)batch * S + (size_t)f0 * HOP;

    char* b0 = (char*)sbuf[warp][0];
    char* b1 = (char*)sbuf[warp][1];
    char* x0p = (char*)xbuf[warp][0];
    char* x1p = (char*)xbuf[warp][1];

    // ---- stage 4 frames ----
    float4 q[4];
    float  t[4];
    #pragma unroll
    for (int s = 0; s < 4; ++s) {
        q[s] = ((const float4*)(base + s * HOP))[lane];     // samples 4l..4l+3
        t[s] = base[s * HOP + 128 + lane];                  // sample 128+l
    }
    float sm[4];
    #pragma unroll
    for (int s = 0; s < 4; ++s)
        sm[s] = ((q[s].x + q[s].y) + (q[s].z + q[s].w)) + t[s];
    #pragma unroll
    for (int off = 16; off; off >>= 1)
        #pragma unroll
        for (int s = 0; s < 4; ++s)
            sm[s] += __shfl_xor_sync(0xffffffffu, sm[s], off);
    float mean[4];
    #pragma unroll
    for (int s = 0; s < 4; ++s) mean[s] = sm[s] / 160.0f;

    float ma[4];
    {
        float cA[4], cB[4], cC[4], cD[4];
        const float* qa = &q[0].x; const float* qb = &q[1].x;
        const float* qc = &q[2].x; const float* qd = &q[3].x;
        #pragma unroll
        for (int i = 0; i < 4; ++i) {
            cA[i] = qa[i] - mean[0]; cB[i] = qb[i] - mean[1];
            cC[i] = qc[i] - mean[2]; cD[i] = qd[i] - mean[3];
        }
        // swizzled buffers
        const int o0 = swz(8 * (64 + 4 * lane));            // bit4 == 0
        *(float4*)(b0 + o0)        = make_float4(cA[0], cB[0], cA[1], cB[1]);
        *(float4*)(b0 + (o0 ^ 16)) = make_float4(cA[2], cB[2], cA[3], cB[3]);
        *(float4*)(b1 + o0)        = make_float4(cC[0], cD[0], cC[1], cD[1]);
        *(float4*)(b1 + (o0 ^ 16)) = make_float4(cC[2], cD[2], cC[3], cD[3]);
        // linear broadcast buffers (pair 4+n at byte 32+8n)
        const int oL = 32 + 32 * lane;
        *(float4*)(x0p + oL)      = make_float4(cA[0], cB[0], cA[1], cB[1]);
        *(float4*)(x0p + oL + 16) = make_float4(cA[2], cB[2], cA[3], cB[3]);
        *(float4*)(x1p + oL)      = make_float4(cC[0], cD[0], cC[1], cD[1]);
        *(float4*)(x1p + oL + 16) = make_float4(cC[2], cD[2], cC[3], cD[3]);

        const float tA = t[0] - mean[0], tB = t[1] - mean[1];
        const float tC = t[2] - mean[2], tD = t[3] - mean[3];
        const int ot = swz(8 * (192 + lane));
        *(float2*)(b0 + ot) = make_float2(tA, tB);
        *(float2*)(b1 + ot) = make_float2(tC, tD);
        const int otL = 1056 + 8 * lane;                    // pair 132+lane
        *(float2*)(x0p + otL) = make_float2(tA, tB);
        *(float2*)(x1p + otL) = make_float2(tC, tD);

        ma[0] = fmaxf(fmaxf(fmaxf(fabsf(cA[0]), fabsf(cA[1])),
                            fmaxf(fabsf(cA[2]), fabsf(cA[3]))), fabsf(tA));
        ma[1] = fmaxf(fmaxf(fmaxf(fabsf(cB[0]), fabsf(cB[1])),
                            fmaxf(fabsf(cB[2]), fabsf(cB[3]))), fabsf(tB));
        ma[2] = fmaxf(fmaxf(fmaxf(fabsf(cC[0]), fabsf(cC[1])),
                            fmaxf(fabsf(cC[2]), fabsf(cC[3]))), fabsf(tC));
        ma[3] = fmaxf(fmaxf(fmaxf(fabsf(cD[0]), fabsf(cD[1])),
                            fmaxf(fabsf(cD[2]), fabsf(cD[3]))), fabsf(tD));
    }
    #pragma unroll
    for (int i = 0; i < 2; ++i) {                           // zero swizzled pad
        const int off = swz(8 * (lane + 32 * i));
        *(ull*)(b0 + off) = 0ull;
        *(ull*)(b1 + off) = 0ull;
    }
    if (lane < 4) {                                         // zero linear pad
        *(ull*)(x0p + 8 * lane) = 0ull;
        *(ull*)(x1p + 8 * lane) = 0ull;
    }
    #pragma unroll
    for (int off = 16; off; off >>= 1)
        #pragma unroll
        for (int s = 0; s < 4; ++s)
            ma[s] = fmaxf(ma[s], __shfl_xor_sync(0xffffffffu, ma[s], off));
    __syncwarp();

    // ---- per-lane geometry ----
    const int hl = lane & 15;
    const int tl = (hl < 15) ? hl : 14;
    const int l0 = MIN_LAG + 8 * tl;
    const int h0 = 20 + 4 * tl;
    const char* mb = (lane < 16) ? b0 : b1;
    const char* xq = (lane < 16) ? x0p : x1p;
    const int l0b = 8 * (64 + l0);

    ull w[12];
    {   // init window d = -4..7
        const int i0 = swz(l0b - 32);
        const int i1 = swz(l0b);
        const int i2 = swz(l0b + 32);
        const ulonglong2 t0 = *(const ulonglong2*)(mb + i0);
        const ulonglong2 t1 = *(const ulonglong2*)(mb + (i0 ^ 16));
        const ulonglong2 t2 = *(const ulonglong2*)(mb + i1);
        const ulonglong2 t3 = *(const ulonglong2*)(mb + (i1 ^ 16));
        const ulonglong2 t4 = *(const ulonglong2*)(mb + i2);
        const ulonglong2 t5 = *(const ulonglong2*)(mb + (i2 ^ 16));
        w[slot(-4)] = t0.x; w[slot(-3)] = t0.y;
        w[slot(-2)] = t1.x; w[slot(-1)] = t1.y;
        w[slot( 0)] = t2.x; w[slot( 1)] = t2.y;
        w[slot( 2)] = t3.x; w[slot( 3)] = t3.y;
        w[slot( 4)] = t4.x; w[slot( 5)] = t4.y;
        w[slot( 6)] = t5.x; w[slot( 7)] = t5.y;
    }

    ull acc[8];
    #pragma unroll
    for (int j = 0; j < 8; ++j) acc[j] = 0ull;

    // broadcast x for chunk 0 (linear buffer: pair 4+n at byte 32+8n)
    ulonglong2 xv0 = *(const ulonglong2*)(xq + 32);
    ulonglong2 xv1 = *(const ulonglong2*)(xq + 48);

    int bro = 64;               // linear byte off of broadcast for n = 4
    int rro = l0b - 64;         // swizzled byte off of refill for chunk n = 0
    int cnt = -h0;              // (next n0) - gate after the += below

#define DO_CHUNK(C, PRE, REF)                                                 \
    {                                                                         \
        const ull x0 = xv0.x, x1 = xv0.y, x2 = xv1.x, x3 = xv1.y;             \
        if (PRE) {                                                            \
            cnt += 4;                                                         \
            const char* xa = xq + ((cnt < 0) ? bro : 0);                      \
            xv0 = *(const ulonglong2*)(xa);                                   \
            xv1 = *(const ulonglong2*)(xa + 16);                              \
            bro += 32;                                                        \
        }                                                                     \
        ulonglong2 ra, rb;                                                    \
        if (REF) {                                                            \
            const int r0 = swz(rro);                                          \
            ra = *(const ulonglong2*)(mb + r0);                               \
            rb = *(const ulonglong2*)(mb + (r0 ^ 16));                        \
            rro -= 32;                                                        \
        }                                                                     \
        _Pragma("unroll")                                                     \
        for (int j = 0; j < 8; ++j)                                           \
            acc[j] = fma2(x0, w[slot(j - 4 * (C) - 0)], acc[j]);              \
        _Pragma("unroll")                                                     \
        for (int j = 0; j < 8; ++j)                                           \
            acc[j] = fma2(x1, w[slot(j - 4 * (C) - 1)], acc[j]);              \
        _Pragma("unroll")                                                     \
        for (int j = 0; j < 8; ++j)                                           \
            acc[j] = fma2(x2, w[slot(j - 4 * (C) - 2)], acc[j]);              \
        _Pragma("unroll")                                                     \
        for (int j = 0; j < 8; ++j)                                           \
            acc[j] = fma2(x3, w[slot(j - 4 * (C) - 3)], acc[j]);              \
        if (REF) {                                                            \
            w[slot(-4 * (C) - 8)] = ra.x;                                     \
            w[slot(-4 * (C) - 7)] = ra.y;                                     \
            w[slot(-4 * (C) - 6)] = rb.x;                                     \
            w[slot(-4 * (C) - 5)] = rb.y;                                     \
        }                                                                     \
    }

    // ---- phase 1: chunks n0 = 0..44 (everyone, own lags) ----
    #pragma unroll 1
    for (int it = 0; it < 4; ++it) {
        DO_CHUNK(0, true, true)
        DO_CHUNK(1, true, true)
        DO_CHUNK(2, true, true)
    }

    // ---- boundary (own lags, all lanes; disjoint from chunk sums) ----
    {
        const int bo = 8 * (64 + h0);                       // 32-aligned
        const int o2 = swz(bo);
        const int o3 = swz(bo + 32);
        const ulonglong2 p2 = *(const ulonglong2*)(mb + o2);
        const ulonglong2 p3 = *(const ulonglong2*)(mb + (o2 ^ 16));
        const ulonglong2 p4 = *(const ulonglong2*)(mb + o3);
        const ulonglong2 p5 = *(const ulonglong2*)(mb + (o3 ^ 16));
        const ull v4 = p2.x, v5 = p2.y, v6 = p3.x, v7 = p3.y;
        const ull v8 = p4.x, v9 = p4.y, v10 = p5.x, v11 = p5.y;

        const ull HALF2 = 0x3F0000003F000000ull;
        const ull h4 = mul2(v4, HALF2);
        const ull h5 = mul2(v5, HALF2);
        const ull h6 = mul2(v6, HALF2);
        const ull h7 = mul2(v7, HALF2);

        acc[0] = fma2(h4, v4,  acc[0]);
        acc[1] = fma2(v4, v5,  acc[1]);
        acc[2] = fma2(v4, v6,  acc[2]);
        acc[3] = fma2(v4, v7,  acc[3]);
        acc[4] = fma2(v4, v8,  acc[4]);
        acc[5] = fma2(v4, v9,  acc[5]);
        acc[6] = fma2(v4, v10, acc[6]);
        acc[7] = fma2(v4, v11, acc[7]);
        acc[2] = fma2(h5, v5,  acc[2]);
        acc[3] = fma2(v5, v6,  acc[3]);
        acc[4] = fma2(v5, v7,  acc[4]);
        acc[5] = fma2(v5, v8,  acc[5]);
        acc[6] = fma2(v5, v9,  acc[6]);
        acc[7] = fma2(v5, v10, acc[7]);
        acc[4] = fma2(h6, v6,  acc[4]);
        acc[5] = fma2(v6, v7,  acc[5]);
        acc[6] = fma2(v6, v8,  acc[6]);
        acc[7] = fma2(v6, v9,  acc[7]);
        acc[6] = fma2(h7, v7,  acc[6]);
        acc[7] = fma2(v7, v8,  acc[7]);
    }

    // ---- per-lane argmax (final for buddies; owners redo after phase 2) ----
    float bLo = -FLT_MAX, bHi = -FLT_MAX;
    int   gLo = 0x7fffffff, gHi = 0x7fffffff;
    {
        float lo, hi;
        #pragma unroll
        for (int j = 0; j < 8; ++j) {
            upk2(acc[j], lo, hi);
            const int l = l0 + j;
            if (lo > bLo) { bLo = lo; gLo = l; }
            if (hi > bHi) { bHi = hi; gHi = l; }
        }
    }

    // ---- phase-2 setup ----
    const bool isOwner = (hl >= 8);
    const bool bAct    = (hl >= 3) && (hl <= 6);
    if (!isOwner) {
        #pragma unroll
        for (int j = 0; j < 8; ++j) acc[j] = 0ull;          // buddy partial accum
    }
    if (isOwner) {
        const int gate = (h0 < 60) ? h0 : 60;
        cnt = 48 - gate;
    } else if (bAct) {
        cnt = 8 - 4 * hl;
    } else {
        cnt = 1000;                                         // always redirect
    }
    if (bAct) {
        bro = 544;                                          // n = 64 prefetch
        rro = l0b - 32;                                     // refill for n = 60
        xv0 = *(const ulonglong2*)(xq + 512);               // x for n = 60
        xv1 = *(const ulonglong2*)(xq + 528);
        // window init for owner lags (l0b' = l0b + 512): d in [-64, -53]
        const int i0 = swz(l0b);
        const int i1 = swz(l0b + 32);
        const int i2 = swz(l0b + 64);
        const ulonglong2 q0 = *(const ulonglong2*)(mb + i0);
        const ulonglong2 q1 = *(const ulonglong2*)(mb + (i0 ^ 16));
        const ulonglong2 q2 = *(const ulonglong2*)(mb + i1);
        const ulonglong2 q3 = *(const ulonglong2*)(mb + (i1 ^ 16));
        const ulonglong2 q4 = *(const ulonglong2*)(mb + i2);
        const ulonglong2 q5 = *(const ulonglong2*)(mb + (i2 ^ 16));
        w[8]  = q0.x; w[9]  = q0.y; w[10] = q1.x; w[11] = q1.y;
        w[0]  = q2.x; w[1]  = q2.y; w[2]  = q3.x; w[3]  = q3.y;
        w[4]  = q4.x; w[5]  = q4.y; w[6]  = q5.x; w[7]  = q5.y;
    }

    // ---- phase 2: 4 unified chunks (owner n0 = 48+4k, buddy n0 = 60+4k) ----
    DO_CHUNK(0, true, true)
    DO_CHUNK(1, true, true)
    DO_CHUNK(2, true, true)
    DO_CHUNK(0, false, false)
#undef DO_CHUNK

    // ---- transfer buddy partials to owners ----
    #pragma unroll
    for (int j = 0; j < 8; ++j) {
        const ull r = __shfl_sync(0xffffffffu, acc[j], (lane - 8) & 31);
        if (isOwner) acc[j] = add2(acc[j], r);
    }

    // ---- owners recompute argmax; buddies keep saved ----
    {
        float nbLo = -FLT_MAX, nbHi = -FLT_MAX;
        int   ngLo = 0x7fffffff, ngHi = 0x7fffffff;
        float lo, hi;
        #pragma unroll
        for (int j = 0; j < 8; ++j) {
            upk2(acc[j], lo, hi);
            const int l = l0 + j;
            if (lo > nbLo) { nbLo = lo; ngLo = l; }
            if (hi > nbHi) { nbHi = hi; ngHi = l; }
        }
        if (isOwner) { bLo = nbLo; gLo = ngLo; bHi = nbHi; gHi = ngHi; }
    }

    if (hl == 15) { bLo = -FLT_MAX; bHi = -FLT_MAX; gLo = gHi = 0x7fffffff; }

    #pragma unroll
    for (int off = 8; off; off >>= 1) {                     // within 16-lane group
        float vL = __shfl_xor_sync(0xffffffffu, bLo, off);
        int   iL = __shfl_xor_sync(0xffffffffu, gLo, off);
        if (vL > bLo || (vL == bLo && iL < gLo)) { bLo = vL; gLo = iL; }
        float vH = __shfl_xor_sync(0xffffffffu, bHi, off);
        int   iH = __shfl_xor_sync(0xffffffffu, gHi, off);
        if (vH > bHi || (vH == bHi && iH < gHi)) { bHi = vH; gHi = iH; }
    }

    if (hl == 0) {
        const int o = g0 + ((lane >> 4) << 1);
        const float mLo = (lane < 16) ? ma[0] : ma[2];
        const float mHi = (lane < 16) ? ma[1] : ma[3];
        out[o]     = (mLo < 1e-8f) ? 0.f : 16000.0f / (float)gLo;
        out[o + 1] = (mHi < 1e-8f) ? 0.f : 16000.0f / (float)gHi;
    }
}

extern "C" void kernel_launch(void* const* d_in, const int* in_sizes, int n_in,
                              void* d_out, int out_size) {
    const float* audio = (const float*)d_in[0];
    float* out = (float*)d_out;

    const int total = in_sizes[0];              // 16 * 1048576
    const int B = NBATCH;
    const int S = total / B;                    // 1048576
    const int T = (S - FRAME) / HOP + 1;        // 4096
    const int frames = B * T;                   // 65536 == out_size
    const int tasks  = frames / 4;              // 16384 warps
    const int blocks = (tasks + 3) / 4;         // 4096 blocks of 4 warps

    pitch_kernel<<<blocks, 128>>>(audio, out, S, T, frames);
}